// round 1
// baseline (speedup 1.0000x reference)
#include <cuda_runtime.h>
#include <cuda_bf16.h>
#include <cstdint>

#define CC    256
#define NH    8
#define DD    32
#define NN    2304
#define BB    4
#define HW    48

// scratch (device globals: no allocations allowed)
__device__ float g_qr[BB*NH*NN*DD];   // RoPE'd Q, [b][h][n][d]
__device__ float g_kr[BB*NH*NN*DD];   // RoPE'd + scaled K
__device__ float g_vr[BB*NH*NN*DD];   // V, [b][h][n][d]
__device__ float g_lepe[BB*NN*CC];    // depthwise conv out, NHWC
__device__ float g_ctx[BB*NN*CC];     // attention out, NHWC

// ---------------------------------------------------------------------------
// Kernel 1: fused QKV projection + bias (+K scaling) + RoPE, writes head-split
// layouts. Block = 256 threads handles 32 rows of X (rows never cross batch:
// 2304 % 32 == 0). Thread c owns output channel c.
// ---------------------------------------------------------------------------
__device__ __forceinline__ void gemm_pass_256(const float* __restrict__ W,
                                              const float* __restrict__ xs,
                                              int c, float* acc)
{
#pragma unroll
    for (int r = 0; r < 32; r++) acc[r] = 0.0f;
    for (int j4 = 0; j4 < 64; j4++) {
        float w0 = W[(j4*4+0)*CC + c];
        float w1 = W[(j4*4+1)*CC + c];
        float w2 = W[(j4*4+2)*CC + c];
        float w3 = W[(j4*4+3)*CC + c];
#pragma unroll
        for (int r = 0; r < 32; r++) {
            float4 xv = *(const float4*)&xs[r*CC + j4*4];
            float a = acc[r];
            a = fmaf(xv.x, w0, a);
            a = fmaf(xv.y, w1, a);
            a = fmaf(xv.z, w2, a);
            a = fmaf(xv.w, w3, a);
            acc[r] = a;
        }
    }
}

__global__ __launch_bounds__(256) void qkv_kernel(
    const float* __restrict__ x,
    const float* __restrict__ sinp, const float* __restrict__ cosp,
    const float* __restrict__ Wq, const float* __restrict__ bq,
    const float* __restrict__ Wk, const float* __restrict__ bk,
    const float* __restrict__ Wv, const float* __restrict__ bv)
{
    __shared__ float xs[32*CC];
    const int t = threadIdx.x;
    const int rowbase = blockIdx.x * 32;

    {
        const float4* src = (const float4*)(x + (size_t)rowbase * CC);
        float4* dst = (float4*)xs;
        for (int i = t; i < 32*CC/4; i += 256) dst[i] = src[i];
    }
    __syncthreads();

    const int c  = t;
    const int dd = c & 31;
    const int h  = c >> 5;
    const float scaling = 0.17677669529663687f;  // 32^-0.5
    float acc[32];

    // ---- Q pass (RoPE) ----
    gemm_pass_256(Wq, xs, c, acc);
    {
        float bias = bq[c];
#pragma unroll 4
        for (int r = 0; r < 32; r++) {
            int row = rowbase + r;
            int b = row / NN, n = row % NN;
            float val = acc[r] + bias;
            float sv = sinp[n*DD + dd];
            float cv = cosp[n*DD + dd];
            float other = __shfl_xor_sync(0xffffffffu, val, 1);
            float rot = (c & 1) ? other : -other;
            g_qr[((size_t)(b*NH + h)*NN + n)*DD + dd] = val*cv + rot*sv;
        }
    }
    // ---- K pass (scale + RoPE) ----
    gemm_pass_256(Wk, xs, c, acc);
    {
        float bias = bk[c];
#pragma unroll 4
        for (int r = 0; r < 32; r++) {
            int row = rowbase + r;
            int b = row / NN, n = row % NN;
            float val = (acc[r] + bias) * scaling;
            float sv = sinp[n*DD + dd];
            float cv = cosp[n*DD + dd];
            float other = __shfl_xor_sync(0xffffffffu, val, 1);
            float rot = (c & 1) ? other : -other;
            g_kr[((size_t)(b*NH + h)*NN + n)*DD + dd] = val*cv + rot*sv;
        }
    }
    // ---- V pass ----
    gemm_pass_256(Wv, xs, c, acc);
    {
        float bias = bv[c];
#pragma unroll 4
        for (int r = 0; r < 32; r++) {
            int row = rowbase + r;
            int b = row / NN, n = row % NN;
            g_vr[((size_t)(b*NH + h)*NN + n)*DD + dd] = acc[r] + bias;
        }
    }
}

// ---------------------------------------------------------------------------
// Kernel 2: depthwise 5x5 conv (LEPE) on V, zero padding 2, + bias. NHWC out.
// ---------------------------------------------------------------------------
__global__ __launch_bounds__(256) void lepe_kernel(
    const float* __restrict__ dw_w, const float* __restrict__ dw_b)
{
    int idx = blockIdx.x * 256 + threadIdx.x;        // < 2359296
    int c  = idx & 255;
    int sp = idx >> 8;
    int xp = sp % HW;
    int t2 = sp / HW;
    int y  = t2 % HW;
    int b  = t2 / HW;
    int h = c >> 5, dd = c & 31;
    const float* vbase = g_vr + (size_t)(b*NH + h)*NN*DD + dd;

    float acc = dw_b[c];
#pragma unroll
    for (int dy = 0; dy < 5; dy++) {
        int yy = y + dy - 2;
        if (yy < 0 || yy >= HW) continue;
#pragma unroll
        for (int dx = 0; dx < 5; dx++) {
            int xx = xp + dx - 2;
            if (xx < 0 || xx >= HW) continue;
            float v = vbase[(size_t)(yy*HW + xx)*DD];
            float w = dw_w[(dy*5 + dx)*CC + c];
            acc = fmaf(v, w, acc);
        }
    }
    g_lepe[idx] = acc;
}

// ---------------------------------------------------------------------------
// Kernel 3: flash attention. Block = 256 threads handles one (h, q-tile of 64)
// and loops over b internally (mask tile reuse in L1/L2). 64-key tiles,
// online softmax, writes ctx in NHWC.
// ---------------------------------------------------------------------------
#define TQ 64
#define TK 64
#define SSTRIDE 68   // 64 + pad, 16B-aligned rows for float4 stores

__global__ __launch_bounds__(256) void attn_kernel(const float* __restrict__ mask)
{
    __shared__ float Qs[TQ*33];
    __shared__ float Ks[TK*33];
    __shared__ float Vs[TK*33];
    __shared__ float Ssh[TQ*SSTRIDE];
    __shared__ float m_s[TQ], l_s[TQ], corr_s[TQ];

    const int t  = threadIdx.x;
    const int q0 = blockIdx.x * TQ;
    const int h  = blockIdx.y;
    const int ti = t >> 4;     // 0..15 -> q rows ti*4..ti*4+3
    const int tj = t & 15;     // 0..15 -> k cols tj*4..  / dd = tj*2..
    const int wrp = t >> 5;    // softmax: rows wrp*8..wrp*8+7
    const int lane = t & 31;

    for (int b = 0; b < BB; b++) {
        __syncthreads();   // protect state arrays from previous b iteration
        for (int i = t; i < TQ; i += 256) { m_s[i] = -1e30f; l_s[i] = 0.0f; }
        const size_t bh = (size_t)(b*NH + h) * NN * DD;
        // load Q tile
        for (int i = t; i < TQ*DD; i += 256) {
            int r = i >> 5, d2 = i & 31;
            Qs[r*33 + d2] = g_qr[bh + (size_t)(q0 + r)*DD + d2];
        }
        float O[4][2] = {{0,0},{0,0},{0,0},{0,0}};
        __syncthreads();

        for (int kt = 0; kt < NN/TK; kt++) {
            const int k0 = kt * TK;
            // load K,V tiles
            for (int i = t; i < TK*DD; i += 256) {
                int r = i >> 5, d2 = i & 31;
                size_t g = bh + (size_t)(k0 + r)*DD + d2;
                Ks[r*33 + d2] = g_kr[g];
                Vs[r*33 + d2] = g_vr[g];
            }
            __syncthreads();

            // ---- scores: 4x4 micro-tile per thread ----
            float s[4][4];
#pragma unroll
            for (int u = 0; u < 4; u++)
#pragma unroll
                for (int v = 0; v < 4; v++) s[u][v] = 0.0f;
#pragma unroll
            for (int d2 = 0; d2 < DD; d2++) {
                float qv[4], kv[4];
#pragma unroll
                for (int u = 0; u < 4; u++) qv[u] = Qs[(ti*4+u)*33 + d2];
#pragma unroll
                for (int v = 0; v < 4; v++) kv[v] = Ks[(tj*4+v)*33 + d2];
#pragma unroll
                for (int u = 0; u < 4; u++)
#pragma unroll
                    for (int v = 0; v < 4; v++)
                        s[u][v] = fmaf(qv[u], kv[v], s[u][v]);
            }
            // add mask, write S tile
#pragma unroll
            for (int u = 0; u < 4; u++) {
                size_t mi = ((size_t)h*NN + (q0 + ti*4 + u))*NN + k0 + tj*4;
                float4 mv = *(const float4*)(mask + mi);
                float4 sv = make_float4(s[u][0]+mv.x, s[u][1]+mv.y,
                                        s[u][2]+mv.z, s[u][3]+mv.w);
                *(float4*)&Ssh[(ti*4+u)*SSTRIDE + tj*4] = sv;
            }
            __syncthreads();

            // ---- online softmax: warp wrp owns 8 rows ----
#pragma unroll
            for (int r = 0; r < 8; r++) {
                int row = wrp*8 + r;
                float a = Ssh[row*SSTRIDE + lane];
                float c2 = Ssh[row*SSTRIDE + lane + 32];
                float mx = fmaxf(a, c2);
#pragma unroll
                for (int off = 16; off; off >>= 1)
                    mx = fmaxf(mx, __shfl_xor_sync(0xffffffffu, mx, off));
                float mold = m_s[row];
                float mnew = fmaxf(mold, mx);
                float p1 = __expf(a  - mnew);
                float p2 = __expf(c2 - mnew);
                Ssh[row*SSTRIDE + lane]      = p1;
                Ssh[row*SSTRIDE + lane + 32] = p2;
                float sm = p1 + p2;
#pragma unroll
                for (int off = 16; off; off >>= 1)
                    sm += __shfl_xor_sync(0xffffffffu, sm, off);
                if (lane == 0) {
                    float cr = __expf(mold - mnew);
                    corr_s[row] = cr;
                    l_s[row] = l_s[row]*cr + sm;
                    m_s[row] = mnew;
                }
            }
            __syncthreads();

            // ---- PV: thread handles 4 q-rows x 2 dims (dd = tj*2, tj*2+1) ----
            {
                float cr[4];
#pragma unroll
                for (int u = 0; u < 4; u++) cr[u] = corr_s[ti*4+u];
#pragma unroll
                for (int u = 0; u < 4; u++) { O[u][0] *= cr[u]; O[u][1] *= cr[u]; }
#pragma unroll 4
                for (int kj = 0; kj < TK; kj++) {
                    float v0 = Vs[kj*33 + tj*2];
                    float v1 = Vs[kj*33 + tj*2 + 1];
#pragma unroll
                    for (int u = 0; u < 4; u++) {
                        float p = Ssh[(ti*4+u)*SSTRIDE + kj];
                        O[u][0] = fmaf(p, v0, O[u][0]);
                        O[u][1] = fmaf(p, v1, O[u][1]);
                    }
                }
            }
            __syncthreads();
        }

        // write ctx NHWC: ctx[b][q][h*32 + dd]
#pragma unroll
        for (int u = 0; u < 4; u++) {
            int rl = ti*4 + u;
            float inv = 1.0f / l_s[rl];
            float2 o2 = make_float2(O[u][0]*inv, O[u][1]*inv);
            size_t oi = ((size_t)b*NN + q0 + rl)*CC + h*DD + tj*2;
            *(float2*)&g_ctx[oi] = o2;
        }
    }
}

// ---------------------------------------------------------------------------
// Kernel 4: output projection  out = (ctx + lepe) @ Wo + bo
// ---------------------------------------------------------------------------
__global__ __launch_bounds__(256) void out_kernel(
    const float* __restrict__ Wo, const float* __restrict__ bo,
    float* __restrict__ out)
{
    __shared__ float xs[32*CC];
    const int t = threadIdx.x;
    const int rowbase = blockIdx.x * 32;
    {
        const float4* a = (const float4*)(g_ctx  + (size_t)rowbase*CC);
        const float4* b = (const float4*)(g_lepe + (size_t)rowbase*CC);
        float4* dst = (float4*)xs;
        for (int i = t; i < 32*CC/4; i += 256) {
            float4 av = a[i], bv = b[i];
            dst[i] = make_float4(av.x+bv.x, av.y+bv.y, av.z+bv.z, av.w+bv.w);
        }
    }
    __syncthreads();
    const int c = t;
    float acc[32];
    gemm_pass_256(Wo, xs, c, acc);
    float bias = bo[c];
#pragma unroll 4
    for (int r = 0; r < 32; r++)
        out[(size_t)(rowbase + r)*CC + c] = acc[r] + bias;
}

// ---------------------------------------------------------------------------
extern "C" void kernel_launch(void* const* d_in, const int* in_sizes, int n_in,
                              void* d_out, int out_size)
{
    const float* x    = (const float*)d_in[0];
    const float* sinp = (const float*)d_in[1];
    const float* cosp = (const float*)d_in[2];
    const float* mask = (const float*)d_in[3];
    const float* Wq   = (const float*)d_in[4];
    const float* bq   = (const float*)d_in[5];
    const float* Wk   = (const float*)d_in[6];
    const float* bk   = (const float*)d_in[7];
    const float* Wv   = (const float*)d_in[8];
    const float* bv   = (const float*)d_in[9];
    const float* dw_w = (const float*)d_in[10];
    const float* dw_b = (const float*)d_in[11];
    const float* Wo   = (const float*)d_in[12];
    const float* bo   = (const float*)d_in[13];
    float* out = (float*)d_out;

    qkv_kernel<<<(BB*NN)/32, 256>>>(x, sinp, cosp, Wq, bq, Wk, bk, Wv, bv);
    lepe_kernel<<<(BB*NN*CC)/256, 256>>>(dw_w, dw_b);
    attn_kernel<<<dim3(NN/TQ, NH), 256>>>(mask);
    out_kernel<<<(BB*NN)/32, 256>>>(Wo, bo, out);
}

// round 4
// speedup vs baseline: 1.6028x; 1.6028x over previous
#include <cuda_runtime.h>
#include <cuda_bf16.h>
#include <cstdint>

#define CC    256
#define NH    8
#define DD    32
#define NN    2304
#define BB    4
#define HW    48

// scratch (device globals: no allocations allowed)
__device__ float g_qr[BB*NH*NN*DD];   // RoPE'd Q (tf32-rounded), [b][h][n][d]
__device__ float g_kr[BB*NH*NN*DD];   // RoPE'd + scaled K (tf32-rounded)
__device__ float g_vr[BB*NH*NN*DD];   // V (full fp32; LEPE needs it), [b][h][n][d]
__device__ float g_lepe[BB*NN*CC];    // depthwise conv out, NHWC
__device__ float g_ctx[BB*NN*CC];     // attention out, NHWC

// ---------------------------------------------------------------------------
// helpers
// ---------------------------------------------------------------------------
__device__ __forceinline__ float to_tf32f(float x) {
    uint32_t u;
    asm("cvt.rna.tf32.f32 %0, %1;" : "=r"(u) : "f"(x));
    return __uint_as_float(u);
}

// D += A(16x8,row) * B(8x8,col), tf32 inputs, fp32 accum
__device__ __forceinline__ void mma_tf32(float* d, const uint32_t* a,
                                         uint32_t b0, uint32_t b1) {
    asm("mma.sync.aligned.m16n8k8.row.col.f32.tf32.tf32.f32 "
        "{%0,%1,%2,%3}, {%4,%5,%6,%7}, {%8,%9}, {%0,%1,%2,%3};"
        : "+f"(d[0]), "+f"(d[1]), "+f"(d[2]), "+f"(d[3])
        : "r"(a[0]), "r"(a[1]), "r"(a[2]), "r"(a[3]), "r"(b0), "r"(b1));
}

// ---------------------------------------------------------------------------
// Kernel 1: fused QKV projection + bias (+K scaling) + RoPE. Q/K outputs are
// tf32-rounded (they only feed tensor-core MMAs); V stays fp32 (LEPE).
// ---------------------------------------------------------------------------
__device__ __forceinline__ void gemm_pass_256(const float* __restrict__ W,
                                              const float* __restrict__ xs,
                                              int c, float* acc)
{
#pragma unroll
    for (int r = 0; r < 32; r++) acc[r] = 0.0f;
    for (int j4 = 0; j4 < 64; j4++) {
        float w0 = W[(j4*4+0)*CC + c];
        float w1 = W[(j4*4+1)*CC + c];
        float w2 = W[(j4*4+2)*CC + c];
        float w3 = W[(j4*4+3)*CC + c];
#pragma unroll
        for (int r = 0; r < 32; r++) {
            float4 xv = *(const float4*)&xs[r*CC + j4*4];
            float a = acc[r];
            a = fmaf(xv.x, w0, a);
            a = fmaf(xv.y, w1, a);
            a = fmaf(xv.z, w2, a);
            a = fmaf(xv.w, w3, a);
            acc[r] = a;
        }
    }
}

__global__ __launch_bounds__(256) void qkv_kernel(
    const float* __restrict__ x,
    const float* __restrict__ sinp, const float* __restrict__ cosp,
    const float* __restrict__ Wq, const float* __restrict__ bq,
    const float* __restrict__ Wk, const float* __restrict__ bk,
    const float* __restrict__ Wv, const float* __restrict__ bv)
{
    __shared__ float xs[32*CC];
    const int t = threadIdx.x;
    const int rowbase = blockIdx.x * 32;

    {
        const float4* src = (const float4*)(x + (size_t)rowbase * CC);
        float4* dst = (float4*)xs;
        for (int i = t; i < 32*CC/4; i += 256) dst[i] = src[i];
    }
    __syncthreads();

    const int c  = t;
    const int dd = c & 31;
    const int h  = c >> 5;
    const float scaling = 0.17677669529663687f;  // 32^-0.5
    float acc[32];

    // ---- Q pass (RoPE) ----
    gemm_pass_256(Wq, xs, c, acc);
    {
        float bias = bq[c];
#pragma unroll 4
        for (int r = 0; r < 32; r++) {
            int row = rowbase + r;
            int b = row / NN, n = row % NN;
            float val = acc[r] + bias;
            float sv = sinp[n*DD + dd];
            float cv = cosp[n*DD + dd];
            float other = __shfl_xor_sync(0xffffffffu, val, 1);
            float rot = (c & 1) ? other : -other;
            g_qr[((size_t)(b*NH + h)*NN + n)*DD + dd] = to_tf32f(val*cv + rot*sv);
        }
    }
    // ---- K pass (scale + RoPE) ----
    gemm_pass_256(Wk, xs, c, acc);
    {
        float bias = bk[c];
#pragma unroll 4
        for (int r = 0; r < 32; r++) {
            int row = rowbase + r;
            int b = row / NN, n = row % NN;
            float val = (acc[r] + bias) * scaling;
            float sv = sinp[n*DD + dd];
            float cv = cosp[n*DD + dd];
            float other = __shfl_xor_sync(0xffffffffu, val, 1);
            float rot = (c & 1) ? other : -other;
            g_kr[((size_t)(b*NH + h)*NN + n)*DD + dd] = to_tf32f(val*cv + rot*sv);
        }
    }
    // ---- V pass ----
    gemm_pass_256(Wv, xs, c, acc);
    {
        float bias = bv[c];
#pragma unroll 4
        for (int r = 0; r < 32; r++) {
            int row = rowbase + r;
            int b = row / NN, n = row % NN;
            g_vr[((size_t)(b*NH + h)*NN + n)*DD + dd] = acc[r] + bias;
        }
    }
}

// ---------------------------------------------------------------------------
// Kernel 2: depthwise 5x5 conv (LEPE) on V, zero padding 2, + bias. NHWC out.
// ---------------------------------------------------------------------------
__global__ __launch_bounds__(256) void lepe_kernel(
    const float* __restrict__ dw_w, const float* __restrict__ dw_b)
{
    int idx = blockIdx.x * 256 + threadIdx.x;        // < 2359296
    int c  = idx & 255;
    int sp = idx >> 8;
    int xp = sp % HW;
    int t2 = sp / HW;
    int y  = t2 % HW;
    int b  = t2 / HW;
    int h = c >> 5, dd = c & 31;
    const float* vbase = g_vr + (size_t)(b*NH + h)*NN*DD + dd;

    float acc = dw_b[c];
#pragma unroll
    for (int dy = 0; dy < 5; dy++) {
        int yy = y + dy - 2;
        if (yy < 0 || yy >= HW) continue;
#pragma unroll
        for (int dx = 0; dx < 5; dx++) {
            int xx = xp + dx - 2;
            if (xx < 0 || xx >= HW) continue;
            float v = vbase[(size_t)(yy*HW + xx)*DD];
            float w = dw_w[(dy*5 + dx)*CC + c];
            acc = fmaf(v, w, acc);
        }
    }
    g_lepe[idx] = acc;
}

// ---------------------------------------------------------------------------
// Kernel 3: flash attention with mma.sync tf32 tensor cores.
// Block = 256 threads (8 warps), q-tile = 128 rows (16 per warp), k-tile = 64.
// PV is done in two 32-column chunks so the P staging buffer is 128x36
// (in-bounds, conflict-free, fits static smem). Loops over b internally so
// mask lines hit L2 on re-reads. Softmax is warp-local in registers.
// ---------------------------------------------------------------------------
#define TK   64
#define KSTR 36   // Ks [64 n][36]: B-frag bank = (4n+d)%32, bijective
#define VSTR 40   // Vs [64 k][40]: B-frag bank = (8k+d)%32, bijective
#define PSTR 36   // Ps [128 m][36]: 32 cols + pad; A-frag bank = (4m+k)%32

__global__ __launch_bounds__(256) void attn_kernel(const float* __restrict__ mask)
{
    __shared__ float Ks[TK*KSTR];    //  9216 B
    __shared__ float Vs[TK*VSTR];    // 10240 B
    __shared__ float Ps[128*PSTR];   // 18432 B (per-warp rows, 32-wide chunks)

    const int t    = threadIdx.x;
    const int w    = t >> 5;
    const int lane = t & 31;
    const int g    = lane >> 2;   // group id: fragment row
    const int tid4 = lane & 3;    // thread-in-group: fragment col
    const int q0   = blockIdx.x * 128;
    const int h    = blockIdx.y;
    const int r0g  = q0 + 16*w + g;   // this thread's first global q row

    for (int b = 0; b < BB; b++) {
        const size_t bh = (size_t)(b*NH + h) * NN * DD;

        // Q fragments held in registers for the whole b-pass (pre-rounded tf32)
        uint32_t qa[4][4];
        {
            const float* qb = g_qr + bh;
#pragma unroll
            for (int kk = 0; kk < 4; kk++) {
                int d0 = kk*8 + tid4;
                qa[kk][0] = __float_as_uint(qb[(size_t)r0g*DD + d0]);
                qa[kk][1] = __float_as_uint(qb[(size_t)(r0g+8)*DD + d0]);
                qa[kk][2] = __float_as_uint(qb[(size_t)r0g*DD + d0+4]);
                qa[kk][3] = __float_as_uint(qb[(size_t)(r0g+8)*DD + d0+4]);
            }
        }

        float m0 = -1e30f, m1 = -1e30f, l0 = 0.0f, l1 = 0.0f;
        float O[4][4];
#pragma unroll
        for (int nt = 0; nt < 4; nt++)
#pragma unroll
            for (int j = 0; j < 4; j++) O[nt][j] = 0.0f;

        const float* mp0 = mask + ((size_t)h*NN + r0g)*NN + 2*tid4;
        const float* mp1 = mp0 + 8*NN;

        for (int kt = 0; kt < NN/TK; kt++) {
            const int k0 = kt * TK;
            __syncthreads();   // all warps done reading previous Ks/Vs
            // cooperative K/V staging (V gets tf32 rounding here)
            for (int i = t; i < TK*DD/4; i += 256) {
                int r  = i >> 3;
                int d4 = (i & 7) << 2;
                float4 kv = *(const float4*)&g_kr[bh + (size_t)(k0+r)*DD + d4];
                *(float4*)&Ks[r*KSTR + d4] = kv;   // already tf32-rounded
                float4 vv = *(const float4*)&g_vr[bh + (size_t)(k0+r)*DD + d4];
                vv.x = to_tf32f(vv.x); vv.y = to_tf32f(vv.y);
                vv.z = to_tf32f(vv.z); vv.w = to_tf32f(vv.w);
                *(float4*)&Vs[r*VSTR + d4] = vv;
            }
            __syncthreads();

            // ---- S = Q K^T : 32 mma per warp ----
            float S[8][4];
#pragma unroll
            for (int nt = 0; nt < 8; nt++)
#pragma unroll
                for (int j = 0; j < 4; j++) S[nt][j] = 0.0f;
#pragma unroll
            for (int kk = 0; kk < 4; kk++) {
#pragma unroll
                for (int nt = 0; nt < 8; nt++) {
                    const float* kb = Ks + (nt*8 + g)*KSTR + kk*8 + tid4;
                    uint32_t b0 = __float_as_uint(kb[0]);
                    uint32_t b1 = __float_as_uint(kb[4]);
                    mma_tf32(S[nt], qa[kk], b0, b1);
                }
            }

            // ---- + mask, row max ----
            float mx0 = -1e30f, mx1 = -1e30f;
#pragma unroll
            for (int nt = 0; nt < 8; nt++) {
                float2 mv0 = *(const float2*)(mp0 + k0 + nt*8);
                float2 mv1 = *(const float2*)(mp1 + k0 + nt*8);
                S[nt][0] += mv0.x; S[nt][1] += mv0.y;
                S[nt][2] += mv1.x; S[nt][3] += mv1.y;
                mx0 = fmaxf(mx0, fmaxf(S[nt][0], S[nt][1]));
                mx1 = fmaxf(mx1, fmaxf(S[nt][2], S[nt][3]));
            }
            mx0 = fmaxf(mx0, __shfl_xor_sync(0xffffffffu, mx0, 1));
            mx0 = fmaxf(mx0, __shfl_xor_sync(0xffffffffu, mx0, 2));
            mx1 = fmaxf(mx1, __shfl_xor_sync(0xffffffffu, mx1, 1));
            mx1 = fmaxf(mx1, __shfl_xor_sync(0xffffffffu, mx1, 2));

            float mn0 = fmaxf(m0, mx0), mn1 = fmaxf(m1, mx1);
            float c0 = __expf(m0 - mn0), c1 = __expf(m1 - mn1);
            m0 = mn0; m1 = mn1;

            // ---- exp in-place (P overwrites S registers), partial sums ----
            float s0 = 0.0f, s1 = 0.0f;
#pragma unroll
            for (int nt = 0; nt < 8; nt++) {
                S[nt][0] = to_tf32f(__expf(S[nt][0] - mn0));
                S[nt][1] = to_tf32f(__expf(S[nt][1] - mn0));
                S[nt][2] = to_tf32f(__expf(S[nt][2] - mn1));
                S[nt][3] = to_tf32f(__expf(S[nt][3] - mn1));
                s0 += S[nt][0] + S[nt][1];
                s1 += S[nt][2] + S[nt][3];
            }
            s0 += __shfl_xor_sync(0xffffffffu, s0, 1);
            s0 += __shfl_xor_sync(0xffffffffu, s0, 2);
            s1 += __shfl_xor_sync(0xffffffffu, s1, 1);
            s1 += __shfl_xor_sync(0xffffffffu, s1, 2);
            l0 = l0*c0 + s0;  l1 = l1*c1 + s1;

#pragma unroll
            for (int nt = 0; nt < 4; nt++) {
                O[nt][0] *= c0; O[nt][1] *= c0;
                O[nt][2] *= c1; O[nt][3] *= c1;
            }

            // ---- O += P V, two 32-col chunks through the 128x36 P buffer ----
            float* prow0 = Ps + (16*w + g)*PSTR + 2*tid4;
            float* prow1 = prow0 + 8*PSTR;
            const float* pr0 = Ps + (16*w + g)*PSTR;
            const float* pr1 = pr0 + 8*PSTR;
#pragma unroll
            for (int ch = 0; ch < 2; ch++) {
#pragma unroll
                for (int nt2 = 0; nt2 < 4; nt2++) {
                    int nt = ch*4 + nt2;
                    *(float2*)(prow0 + nt2*8) = make_float2(S[nt][0], S[nt][1]);
                    *(float2*)(prow1 + nt2*8) = make_float2(S[nt][2], S[nt][3]);
                }
                __syncwarp();   // P chunk visible to this warp's lanes
#pragma unroll
                for (int kk2 = 0; kk2 < 4; kk2++) {
                    int kbp = kk2*8 + tid4;        // P col within chunk
                    uint32_t A[4];
                    A[0] = __float_as_uint(pr0[kbp]);
                    A[1] = __float_as_uint(pr1[kbp]);
                    A[2] = __float_as_uint(pr0[kbp+4]);
                    A[3] = __float_as_uint(pr1[kbp+4]);
                    int kv = ch*32 + kk2*8 + tid4; // V row within tile
                    const float* vb0 = Vs + kv*VSTR + g;
                    const float* vb1 = Vs + (kv+4)*VSTR + g;
#pragma unroll
                    for (int nt = 0; nt < 4; nt++) {
                        uint32_t b0 = __float_as_uint(vb0[nt*8]);
                        uint32_t b1 = __float_as_uint(vb1[nt*8]);
                        mma_tf32(O[nt], A, b0, b1);
                    }
                }
                __syncwarp();   // done reading chunk before overwrite
            }
        }

        // ---- epilogue: normalize, write ctx NHWC ----
        float inv0 = 1.0f / l0, inv1 = 1.0f / l1;
#pragma unroll
        for (int nt = 0; nt < 4; nt++) {
            size_t o0 = ((size_t)b*NN + r0g)*CC + h*DD + nt*8 + 2*tid4;
            size_t o1 = ((size_t)b*NN + r0g + 8)*CC + h*DD + nt*8 + 2*tid4;
            *(float2*)&g_ctx[o0] = make_float2(O[nt][0]*inv0, O[nt][1]*inv0);
            *(float2*)&g_ctx[o1] = make_float2(O[nt][2]*inv1, O[nt][3]*inv1);
        }
    }
}

// ---------------------------------------------------------------------------
// Kernel 4: output projection  out = (ctx + lepe) @ Wo + bo
// ---------------------------------------------------------------------------
__global__ __launch_bounds__(256) void out_kernel(
    const float* __restrict__ Wo, const float* __restrict__ bo,
    float* __restrict__ out)
{
    __shared__ float xs[32*CC];
    const int t = threadIdx.x;
    const int rowbase = blockIdx.x * 32;
    {
        const float4* a = (const float4*)(g_ctx  + (size_t)rowbase*CC);
        const float4* b = (const float4*)(g_lepe + (size_t)rowbase*CC);
        float4* dst = (float4*)xs;
        for (int i = t; i < 32*CC/4; i += 256) {
            float4 av = a[i], bv = b[i];
            dst[i] = make_float4(av.x+bv.x, av.y+bv.y, av.z+bv.z, av.w+bv.w);
        }
    }
    __syncthreads();
    const int c = t;
    float acc[32];
    gemm_pass_256(Wo, xs, c, acc);
    float bias = bo[c];
#pragma unroll 4
    for (int r = 0; r < 32; r++)
        out[(size_t)(rowbase + r)*CC + c] = acc[r] + bias;
}

// ---------------------------------------------------------------------------
extern "C" void kernel_launch(void* const* d_in, const int* in_sizes, int n_in,
                              void* d_out, int out_size)
{
    const float* x    = (const float*)d_in[0];
    const float* sinp = (const float*)d_in[1];
    const float* cosp = (const float*)d_in[2];
    const float* mask = (const float*)d_in[3];
    const float* Wq   = (const float*)d_in[4];
    const float* bq   = (const float*)d_in[5];
    const float* Wk   = (const float*)d_in[6];
    const float* bk   = (const float*)d_in[7];
    const float* Wv   = (const float*)d_in[8];
    const float* bv   = (const float*)d_in[9];
    const float* dw_w = (const float*)d_in[10];
    const float* dw_b = (const float*)d_in[11];
    const float* Wo   = (const float*)d_in[12];
    const float* bo   = (const float*)d_in[13];
    float* out = (float*)d_out;

    qkv_kernel<<<(BB*NN)/32, 256>>>(x, sinp, cosp, Wq, bq, Wk, bk, Wv, bv);
    lepe_kernel<<<(BB*NN*CC)/256, 256>>>(dw_w, dw_b);
    attn_kernel<<<dim3(NN/128, NH), 256>>>(mask);
    out_kernel<<<(BB*NN)/32, 256>>>(Wo, bo, out);
}

// round 7
// speedup vs baseline: 3.1528x; 1.9670x over previous
#include <cuda_runtime.h>
#include <cuda_bf16.h>
#include <cstdint>

#define CC    256
#define NH    8
#define DD    32
#define NN    2304
#define BB    4
#define HW    48

// scratch (device globals: no allocations allowed)
__device__ float g_qr[BB*NH*NN*DD];   // RoPE'd Q (tf32-rounded), [b][h][n][d]
__device__ float g_kr[BB*NH*NN*DD];   // RoPE'd + scaled K (tf32-rounded)
__device__ float g_vr[BB*NH*NN*DD];   // V (full fp32; LEPE needs it), [b][h][n][d]
__device__ float g_lepe[BB*NN*CC];    // depthwise conv out, NHWC
__device__ float g_ctx[BB*NN*CC];     // attention out, NHWC

// ---------------------------------------------------------------------------
// helpers
// ---------------------------------------------------------------------------
__device__ __forceinline__ float to_tf32f(float x) {
    uint32_t u;
    asm("cvt.rna.tf32.f32 %0, %1;" : "=r"(u) : "f"(x));
    return __uint_as_float(u);
}

// D += A(16x8,row) * B(8x8,col), tf32 inputs, fp32 accum
__device__ __forceinline__ void mma_tf32(float* d, const uint32_t* a,
                                         uint32_t b0, uint32_t b1) {
    asm("mma.sync.aligned.m16n8k8.row.col.f32.tf32.tf32.f32 "
        "{%0,%1,%2,%3}, {%4,%5,%6,%7}, {%8,%9}, {%0,%1,%2,%3};"
        : "+f"(d[0]), "+f"(d[1]), "+f"(d[2]), "+f"(d[3])
        : "r"(a[0]), "r"(a[1]), "r"(a[2]), "r"(a[3]), "r"(b0), "r"(b1));
}

// ---------------------------------------------------------------------------
// Tensor-core tf32 GEMM tile machinery: block computes a 128x64 tile of
// X[9216x256] @ W[256x256]. 8 warps as 4x2; warp tile 32x32; frags 2(m)x4(n).
// XSTR=44: A-frag bank (12g+t4)%32 bijective, rows 16B-aligned (176B).
// WSTR=36: B-frag bank (4g+t4)%32 bijective.
// ---------------------------------------------------------------------------
#define XSTR 44
#define WSTR 36

// stage one 64x32 transposed W chunk: Ws[n][k] = tf32(W[k0+k][n0+n])
__device__ __forceinline__ void stage_W(const float* __restrict__ W,
                                        int k0, int n0, float* Ws, int t)
{
#pragma unroll
    for (int j = 0; j < 2; j++) {
        int i = t + j*256;                 // 0..511
        int k = i >> 4, n4 = (i & 15) * 4;
        float4 v = *(const float4*)&W[(size_t)(k0+k)*CC + n0 + n4];
        Ws[(n4+0)*WSTR + k] = to_tf32f(v.x);
        Ws[(n4+1)*WSTR + k] = to_tf32f(v.y);
        Ws[(n4+2)*WSTR + k] = to_tf32f(v.z);
        Ws[(n4+3)*WSTR + k] = to_tf32f(v.w);
    }
}

// after staging: accumulate 32x32 warp tile for one 32-deep K chunk
__device__ __forceinline__ void mm_chunk(const float* Xs, const float* Ws,
                                         int wm, int wn, int g, int t4,
                                         float C[2][4][4])
{
#pragma unroll
    for (int ks = 0; ks < 4; ks++) {
        int kk = ks*8;
        uint32_t a[2][4];
#pragma unroll
        for (int mi = 0; mi < 2; mi++) {
            const float* ab = Xs + (wm*32 + mi*16 + g)*XSTR + kk + t4;
            a[mi][0] = __float_as_uint(ab[0]);
            a[mi][1] = __float_as_uint(ab[8*XSTR]);
            a[mi][2] = __float_as_uint(ab[4]);
            a[mi][3] = __float_as_uint(ab[8*XSTR + 4]);
        }
#pragma unroll
        for (int ni = 0; ni < 4; ni++) {
            const float* bb = Ws + (wn*32 + ni*8 + g)*WSTR + kk + t4;
            uint32_t b0 = __float_as_uint(bb[0]);
            uint32_t b1 = __float_as_uint(bb[4]);
            mma_tf32(C[0][ni], a[0], b0, b1);
            mma_tf32(C[1][ni], a[1], b0, b1);
        }
    }
}

// ---------------------------------------------------------------------------
// Kernel 1: QKV projection as tensor GEMM + fused bias/scale/RoPE epilogue.
// grid (72, 12): y = which*4 + n-tile. RoPE pair (even,odd col) is c0/c1 of
// one thread -> thread-local rotation.
// ---------------------------------------------------------------------------
__global__ __launch_bounds__(256) void qkv_mm_kernel(
    const float* __restrict__ x,
    const float* __restrict__ sinp, const float* __restrict__ cosp,
    const float* __restrict__ Wq, const float* __restrict__ bq,
    const float* __restrict__ Wk, const float* __restrict__ bk,
    const float* __restrict__ Wv, const float* __restrict__ bv)
{
    __shared__ float Xs[128*XSTR];
    __shared__ float Ws[64*WSTR];
    const int t = threadIdx.x;
    const int w = t >> 5, lane = t & 31, g = lane >> 2, t4 = lane & 3;
    const int wm = w >> 1, wn = w & 1;
    const int mb = blockIdx.x * 128;
    const int which = blockIdx.y >> 2;
    const int n0 = (blockIdx.y & 3) * 64;
    const float* W = (which == 0) ? Wq : (which == 1) ? Wk : Wv;
    const float* bias = (which == 0) ? bq : (which == 1) ? bk : bv;

    float C[2][4][4] = {};
    for (int k0 = 0; k0 < CC; k0 += 32) {
        __syncthreads();
#pragma unroll
        for (int j = 0; j < 4; j++) {
            int i = t + j*256;             // 0..1023
            int r = i >> 3, c4 = (i & 7) * 4;
            float4 v = *(const float4*)&x[(size_t)(mb+r)*CC + k0 + c4];
            v.x = to_tf32f(v.x); v.y = to_tf32f(v.y);
            v.z = to_tf32f(v.z); v.w = to_tf32f(v.w);
            *(float4*)&Xs[r*XSTR + c4] = v;
        }
        stage_W(W, k0, n0, Ws, t);
        __syncthreads();
        mm_chunk(Xs, Ws, wm, wn, g, t4, C);
    }

    // ---- epilogue ----
    const float scaling = 0.17677669529663687f;  // 32^-0.5
#pragma unroll
    for (int mi = 0; mi < 2; mi++) {
        int gr0 = mb + wm*32 + mi*16 + g;
#pragma unroll
        for (int ni = 0; ni < 4; ni++) {
            int c0 = n0 + wn*32 + ni*8 + 2*t4;   // even channel
            float2 bv2 = *(const float2*)&bias[c0];
            int dd = c0 & 31, h = c0 >> 5;
#pragma unroll
            for (int rr = 0; rr < 2; rr++) {
                int grow = gr0 + rr*8;
                int b = grow / NN, n = grow - b*NN;
                float ve = C[mi][ni][2*rr+0] + bv2.x;
                float vo = C[mi][ni][2*rr+1] + bv2.y;
                size_t hoff = ((size_t)(b*NH + h)*NN + n)*DD + dd;
                if (which == 2) {
                    *(float2*)&g_vr[hoff] = make_float2(ve, vo);
                } else {
                    if (which == 1) { ve *= scaling; vo *= scaling; }
                    float2 sc = *(const float2*)&sinp[n*DD + dd];
                    float2 cs = *(const float2*)&cosp[n*DD + dd];
                    float oe = ve*cs.x - vo*sc.x;
                    float oo = vo*cs.y + ve*sc.y;
                    float* dst = (which == 0) ? g_qr : g_kr;
                    *(float2*)&dst[hoff] = make_float2(to_tf32f(oe), to_tf32f(oo));
                }
            }
        }
    }
}

// ---------------------------------------------------------------------------
// Kernel 2: depthwise 5x5 conv (LEPE) on V, zero padding 2, + bias. NHWC out.
// ---------------------------------------------------------------------------
__global__ __launch_bounds__(256) void lepe_kernel(
    const float* __restrict__ dw_w, const float* __restrict__ dw_b)
{
    int idx = blockIdx.x * 256 + threadIdx.x;        // < 2359296
    int c  = idx & 255;
    int sp = idx >> 8;
    int xp = sp % HW;
    int t2 = sp / HW;
    int y  = t2 % HW;
    int b  = t2 / HW;
    int h = c >> 5, dd = c & 31;
    const float* vbase = g_vr + (size_t)(b*NH + h)*NN*DD + dd;

    float acc = dw_b[c];
#pragma unroll
    for (int dy = 0; dy < 5; dy++) {
        int yy = y + dy - 2;
        if (yy < 0 || yy >= HW) continue;
#pragma unroll
        for (int dx = 0; dx < 5; dx++) {
            int xx = xp + dx - 2;
            if (xx < 0 || xx >= HW) continue;
            float v = vbase[(size_t)(yy*HW + xx)*DD];
            float w = dw_w[(dy*5 + dx)*CC + c];
            acc = fmaf(v, w, acc);
        }
    }
    g_lepe[idx] = acc;
}

// ---------------------------------------------------------------------------
// Kernel 3: flash attention with mma.sync tf32 tensor cores.
// grid (BB, 18, 8): b fastest-varying so same-(q0,h) blocks co-schedule and
// share mask lines in L2. 2 blocks/SM. PV in two 32-col chunks through a
// 128x36 P buffer (per-warp rows, syncwarp only).
// ---------------------------------------------------------------------------
#define TK   64
#define KSTR 36   // Ks [64 n][36]: B-frag bank = (4n+d)%32, bijective
#define VSTR 40   // Vs [64 k][40]: B-frag bank = (8k+d)%32, bijective
#define PSTR 36   // Ps [128 m][36]: 32 cols + pad; A-frag bank = (4m+k)%32

__global__ __launch_bounds__(256, 2) void attn_kernel(const float* __restrict__ mask)
{
    __shared__ float Ks[TK*KSTR];    //  9216 B
    __shared__ float Vs[TK*VSTR];    // 10240 B
    __shared__ float Ps[128*PSTR];   // 18432 B (per-warp rows, 32-wide chunks)

    const int t    = threadIdx.x;
    const int w    = t >> 5;
    const int lane = t & 31;
    const int g    = lane >> 2;   // group id: fragment row
    const int tid4 = lane & 3;    // thread-in-group: fragment col
    const int b    = blockIdx.x;
    const int q0   = blockIdx.y * 128;
    const int h    = blockIdx.z;
    const int r0g  = q0 + 16*w + g;   // this thread's first global q row

    const size_t bh = (size_t)(b*NH + h) * NN * DD;

    // Q fragments held in registers for the whole pass (pre-rounded tf32)
    uint32_t qa[4][4];
    {
        const float* qb = g_qr + bh;
#pragma unroll
        for (int kk = 0; kk < 4; kk++) {
            int d0 = kk*8 + tid4;
            qa[kk][0] = __float_as_uint(qb[(size_t)r0g*DD + d0]);
            qa[kk][1] = __float_as_uint(qb[(size_t)(r0g+8)*DD + d0]);
            qa[kk][2] = __float_as_uint(qb[(size_t)r0g*DD + d0+4]);
            qa[kk][3] = __float_as_uint(qb[(size_t)(r0g+8)*DD + d0+4]);
        }
    }

    float m0 = -1e30f, m1 = -1e30f, l0 = 0.0f, l1 = 0.0f;
    float O[4][4];
#pragma unroll
    for (int nt = 0; nt < 4; nt++)
#pragma unroll
        for (int j = 0; j < 4; j++) O[nt][j] = 0.0f;

    const float* mp0 = mask + ((size_t)h*NN + r0g)*NN + 2*tid4;
    const float* mp1 = mp0 + 8*NN;

    for (int kt = 0; kt < NN/TK; kt++) {
        const int k0 = kt * TK;
        __syncthreads();   // all warps done reading previous Ks/Vs
        // cooperative K/V staging (V gets tf32 rounding here)
        for (int i = t; i < TK*DD/4; i += 256) {
            int r  = i >> 3;
            int d4 = (i & 7) << 2;
            float4 kv = *(const float4*)&g_kr[bh + (size_t)(k0+r)*DD + d4];
            *(float4*)&Ks[r*KSTR + d4] = kv;   // already tf32-rounded
            float4 vv = *(const float4*)&g_vr[bh + (size_t)(k0+r)*DD + d4];
            vv.x = to_tf32f(vv.x); vv.y = to_tf32f(vv.y);
            vv.z = to_tf32f(vv.z); vv.w = to_tf32f(vv.w);
            *(float4*)&Vs[r*VSTR + d4] = vv;
        }
        __syncthreads();

        // ---- S = Q K^T : 32 mma per warp ----
        float S[8][4];
#pragma unroll
        for (int nt = 0; nt < 8; nt++)
#pragma unroll
            for (int j = 0; j < 4; j++) S[nt][j] = 0.0f;
#pragma unroll
        for (int kk = 0; kk < 4; kk++) {
#pragma unroll
            for (int nt = 0; nt < 8; nt++) {
                const float* kb = Ks + (nt*8 + g)*KSTR + kk*8 + tid4;
                uint32_t b0 = __float_as_uint(kb[0]);
                uint32_t b1 = __float_as_uint(kb[4]);
                mma_tf32(S[nt], qa[kk], b0, b1);
            }
        }

        // ---- + mask, row max ----
        float mx0 = -1e30f, mx1 = -1e30f;
#pragma unroll
        for (int nt = 0; nt < 8; nt++) {
            float2 mv0 = *(const float2*)(mp0 + k0 + nt*8);
            float2 mv1 = *(const float2*)(mp1 + k0 + nt*8);
            S[nt][0] += mv0.x; S[nt][1] += mv0.y;
            S[nt][2] += mv1.x; S[nt][3] += mv1.y;
            mx0 = fmaxf(mx0, fmaxf(S[nt][0], S[nt][1]));
            mx1 = fmaxf(mx1, fmaxf(S[nt][2], S[nt][3]));
        }
        mx0 = fmaxf(mx0, __shfl_xor_sync(0xffffffffu, mx0, 1));
        mx0 = fmaxf(mx0, __shfl_xor_sync(0xffffffffu, mx0, 2));
        mx1 = fmaxf(mx1, __shfl_xor_sync(0xffffffffu, mx1, 1));
        mx1 = fmaxf(mx1, __shfl_xor_sync(0xffffffffu, mx1, 2));

        float mn0 = fmaxf(m0, mx0), mn1 = fmaxf(m1, mx1);
        float c0 = __expf(m0 - mn0), c1 = __expf(m1 - mn1);
        m0 = mn0; m1 = mn1;

        // ---- exp in-place (P overwrites S registers), partial sums ----
        float s0 = 0.0f, s1 = 0.0f;
#pragma unroll
        for (int nt = 0; nt < 8; nt++) {
            S[nt][0] = to_tf32f(__expf(S[nt][0] - mn0));
            S[nt][1] = to_tf32f(__expf(S[nt][1] - mn0));
            S[nt][2] = to_tf32f(__expf(S[nt][2] - mn1));
            S[nt][3] = to_tf32f(__expf(S[nt][3] - mn1));
            s0 += S[nt][0] + S[nt][1];
            s1 += S[nt][2] + S[nt][3];
        }
        s0 += __shfl_xor_sync(0xffffffffu, s0, 1);
        s0 += __shfl_xor_sync(0xffffffffu, s0, 2);
        s1 += __shfl_xor_sync(0xffffffffu, s1, 1);
        s1 += __shfl_xor_sync(0xffffffffu, s1, 2);
        l0 = l0*c0 + s0;  l1 = l1*c1 + s1;

#pragma unroll
        for (int nt = 0; nt < 4; nt++) {
            O[nt][0] *= c0; O[nt][1] *= c0;
            O[nt][2] *= c1; O[nt][3] *= c1;
        }

        // ---- O += P V, two 32-col chunks through the 128x36 P buffer ----
        float* prow0 = Ps + (16*w + g)*PSTR + 2*tid4;
        float* prow1 = prow0 + 8*PSTR;
        const float* pr0 = Ps + (16*w + g)*PSTR;
        const float* pr1 = pr0 + 8*PSTR;
#pragma unroll
        for (int ch = 0; ch < 2; ch++) {
#pragma unroll
            for (int nt2 = 0; nt2 < 4; nt2++) {
                int nt = ch*4 + nt2;
                *(float2*)(prow0 + nt2*8) = make_float2(S[nt][0], S[nt][1]);
                *(float2*)(prow1 + nt2*8) = make_float2(S[nt][2], S[nt][3]);
            }
            __syncwarp();   // P chunk visible to this warp's lanes
#pragma unroll
            for (int kk2 = 0; kk2 < 4; kk2++) {
                int kbp = kk2*8 + tid4;        // P col within chunk
                uint32_t A[4];
                A[0] = __float_as_uint(pr0[kbp]);
                A[1] = __float_as_uint(pr1[kbp]);
                A[2] = __float_as_uint(pr0[kbp+4]);
                A[3] = __float_as_uint(pr1[kbp+4]);
                int kv = ch*32 + kk2*8 + tid4; // V row within tile
                const float* vb0 = Vs + kv*VSTR + g;
                const float* vb1 = Vs + (kv+4)*VSTR + g;
#pragma unroll
                for (int nt = 0; nt < 4; nt++) {
                    uint32_t b0 = __float_as_uint(vb0[nt*8]);
                    uint32_t b1 = __float_as_uint(vb1[nt*8]);
                    mma_tf32(O[nt], A, b0, b1);
                }
            }
            __syncwarp();   // done reading chunk before overwrite
        }
    }

    // ---- epilogue: normalize, write ctx NHWC ----
    float inv0 = 1.0f / l0, inv1 = 1.0f / l1;
#pragma unroll
    for (int nt = 0; nt < 4; nt++) {
        size_t o0 = ((size_t)b*NN + r0g)*CC + h*DD + nt*8 + 2*tid4;
        size_t o1 = ((size_t)b*NN + r0g + 8)*CC + h*DD + nt*8 + 2*tid4;
        *(float2*)&g_ctx[o0] = make_float2(O[nt][0]*inv0, O[nt][1]*inv0);
        *(float2*)&g_ctx[o1] = make_float2(O[nt][2]*inv1, O[nt][3]*inv1);
    }
}

// ---------------------------------------------------------------------------
// Kernel 4: output projection as tensor GEMM: out = (ctx + lepe) @ Wo + bo
// grid (72, 4).
// ---------------------------------------------------------------------------
__global__ __launch_bounds__(256) void out_mm_kernel(
    const float* __restrict__ Wo, const float* __restrict__ bo,
    float* __restrict__ out)
{
    __shared__ float Xs[128*XSTR];
    __shared__ float Ws[64*WSTR];
    const int t = threadIdx.x;
    const int w = t >> 5, lane = t & 31, g = lane >> 2, t4 = lane & 3;
    const int wm = w >> 1, wn = w & 1;
    const int mb = blockIdx.x * 128;
    const int n0 = blockIdx.y * 64;

    float C[2][4][4] = {};
    for (int k0 = 0; k0 < CC; k0 += 32) {
        __syncthreads();
#pragma unroll
        for (int j = 0; j < 4; j++) {
            int i = t + j*256;
            int r = i >> 3, c4 = (i & 7) * 4;
            size_t goff = (size_t)(mb+r)*CC + k0 + c4;
            float4 a = *(const float4*)&g_ctx[goff];
            float4 b = *(const float4*)&g_lepe[goff];
            float4 v;
            v.x = to_tf32f(a.x + b.x); v.y = to_tf32f(a.y + b.y);
            v.z = to_tf32f(a.z + b.z); v.w = to_tf32f(a.w + b.w);
            *(float4*)&Xs[r*XSTR + c4] = v;
        }
        stage_W(Wo, k0, n0, Ws, t);
        __syncthreads();
        mm_chunk(Xs, Ws, wm, wn, g, t4, C);
    }

#pragma unroll
    for (int mi = 0; mi < 2; mi++) {
        int gr0 = mb + wm*32 + mi*16 + g;
#pragma unroll
        for (int ni = 0; ni < 4; ni++) {
            int c0 = n0 + wn*32 + ni*8 + 2*t4;
            float2 bv2 = *(const float2*)&bo[c0];
#pragma unroll
            for (int rr = 0; rr < 2; rr++) {
                int grow = gr0 + rr*8;
                float2 o2 = make_float2(C[mi][ni][2*rr+0] + bv2.x,
                                        C[mi][ni][2*rr+1] + bv2.y);
                *(float2*)&out[(size_t)grow*CC + c0] = o2;
            }
        }
    }
}

// ---------------------------------------------------------------------------
extern "C" void kernel_launch(void* const* d_in, const int* in_sizes, int n_in,
                              void* d_out, int out_size)
{
    const float* x    = (const float*)d_in[0];
    const float* sinp = (const float*)d_in[1];
    const float* cosp = (const float*)d_in[2];
    const float* mask = (const float*)d_in[3];
    const float* Wq   = (const float*)d_in[4];
    const float* bq   = (const float*)d_in[5];
    const float* Wk   = (const float*)d_in[6];
    const float* bk   = (const float*)d_in[7];
    const float* Wv   = (const float*)d_in[8];
    const float* bv   = (const float*)d_in[9];
    const float* dw_w = (const float*)d_in[10];
    const float* dw_b = (const float*)d_in[11];
    const float* Wo   = (const float*)d_in[12];
    const float* bo   = (const float*)d_in[13];
    float* out = (float*)d_out;

    qkv_mm_kernel<<<dim3((BB*NN)/128, 12), 256>>>(x, sinp, cosp,
                                                  Wq, bq, Wk, bk, Wv, bv);
    lepe_kernel<<<(BB*NN*CC)/256, 256>>>(dw_w, dw_b);
    attn_kernel<<<dim3(BB, NN/128, NH), 256>>>(mask);
    out_mm_kernel<<<dim3((BB*NN)/128, 4), 256>>>(Wo, bo, out);
}